// round 5
// baseline (speedup 1.0000x reference)
#include <cuda_runtime.h>
#include <cstdint>
#include <cstddef>

#define B_  256
#define C_  4
#define N_  64
#define F_  256
#define OC_ 8
#define OF_ 256

// Scratch (no allocations allowed)
__device__ float g_z[B_ * 2 * C_ * F_];    // 2 MB : concat(h, x) rows for GEMM
__device__ float g_w[B_ * N_];             // softmax weights
__device__ float g_s2[B_ * N_];            // raw neighbor logits

__device__ __forceinline__ float sqrt_ap(float v) {
    float r; asm("sqrt.approx.f32 %0, %1;" : "=f"(r) : "f"(v)); return r;
}
__device__ __forceinline__ float rcp_ap(float v) {
    float r; asm("rcp.approx.f32 %0, %1;" : "=f"(r) : "f"(v)); return r;
}

// ---------------------------------------------------------------------------
// Kernel 1a: s2 logits. Grid 1024 = (b, quarter); each block: 16 neighbors.
// 4x the threads of the old k1 => MLP-limited BW up.
// ---------------------------------------------------------------------------
__global__ __launch_bounds__(256) void k1a_logits(
    const float* __restrict__ nb, const float* __restrict__ Wa2)
{
    __shared__ float ws2[256];
    const int b = blockIdx.x >> 2, quarter = blockIdx.x & 3;
    const int t = threadIdx.x;
    const int lane = t & 31, w = t >> 5;

    ws2[t] = Wa2[t] + Wa2[256 + t] + Wa2[512 + t] + Wa2[768 + t];
    __syncthreads();

    const float* nbb = nb + (size_t)b * 65536;
    #pragma unroll
    for (int j = 0; j < 2; j++) {
        const int n = quarter * 16 + w * 2 + j;
        const float4* np = (const float4*)(nbb + n * 1024);
        float acc = 0.f;
        #pragma unroll
        for (int it = 0; it < 8; it++) {
            float4 q = np[it * 32 + lane];
            int f = (it * 128 + lane * 4) & 255;
            acc += q.x * ws2[f] + q.y * ws2[f + 1] + q.z * ws2[f + 2] + q.w * ws2[f + 3];
        }
        #pragma unroll
        for (int o = 16; o > 0; o >>= 1) acc += __shfl_xor_sync(0xffffffffu, acc, o);
        if (lane == 0) g_s2[b * 64 + n] = acc;
    }
}

// ---------------------------------------------------------------------------
// Kernel 1b: s1 + softmax weights; copy x into z channels 4..7. Grid 256.
// ---------------------------------------------------------------------------
__global__ __launch_bounds__(256) void k1b_softmax(
    const float* __restrict__ x, const float* __restrict__ Wa1)
{
    __shared__ float red[8];
    const int b = blockIdx.x;
    const int t = threadIdx.x;
    const int lane = t & 31, w = t >> 5;

    float w1 = Wa1[t] + Wa1[256 + t] + Wa1[512 + t] + Wa1[768 + t];

    float xs = 0.f;
    #pragma unroll
    for (int c = 0; c < 4; c++) {
        float xv = x[(b * 4 + c) * 256 + t];
        g_z[b * 2048 + (4 + c) * 256 + t] = xv;
        xs += xv;
    }
    float p = xs * w1;
    #pragma unroll
    for (int o = 16; o > 0; o >>= 1) p += __shfl_xor_sync(0xffffffffu, p, o);
    if (lane == 0) red[w] = p;
    __syncthreads();

    if (w == 0) {
        float s1v = red[lane & 7];
        #pragma unroll
        for (int o = 4; o > 0; o >>= 1) s1v += __shfl_xor_sync(0xffffffffu, s1v, o);
        float l0 = s1v * g_s2[b * 64 + lane];
        float l1 = s1v * g_s2[b * 64 + lane + 32];
        float m = fmaxf(l0, l1);
        #pragma unroll
        for (int o = 16; o > 0; o >>= 1) m = fmaxf(m, __shfl_xor_sync(0xffffffffu, m, o));
        float e0 = __expf(l0 - m), e1 = __expf(l1 - m);
        float s = e0 + e1;
        #pragma unroll
        for (int o = 16; o > 0; o >>= 1) s += __shfl_xor_sync(0xffffffffu, s, o);
        float inv = 1.f / s;
        g_w[b * 64 + lane]      = e0 * inv;
        g_w[b * 64 + lane + 32] = e1 * inv;
    }
}

// ---------------------------------------------------------------------------
// Kernel 2: v (L2-resident neighbor) + adj + fused h.
// ---------------------------------------------------------------------------
__global__ __launch_bounds__(256) void k2_adj(
    const float* __restrict__ x, const float* __restrict__ nb,
    float* __restrict__ adj)
{
    __shared__ float xs[256], vs[256], us[256], idn[256];
    __shared__ float wsm[64];
    __shared__ float pden[4 * 256];

    const int bc = blockIdx.x;
    const int b = bc >> 2, c = bc & 3;
    const int t = threadIdx.x;

    if (t < 64) wsm[t] = g_w[b * 64 + t];
    xs[t] = x[bc * 256 + t];
    __syncthreads();

    {
        const float* nbp = nb + ((size_t)b * 256 + c) * 256 + t;
        float acc = 0.f;
        #pragma unroll 8
        for (int n = 0; n < 64; n++) acc += wsm[n] * nbp[(size_t)n * 1024];
        vs[t] = acc;
    }
    __syncthreads();

    const int r = t >> 6, cg = t & 63;
    const int i0 = r * 64;
    float xc[4], vc[4];
    #pragma unroll
    for (int j = 0; j < 4; j++) { xc[j] = xs[4 * cg + j]; vc[j] = vs[4 * cg + j]; }

    float d[4] = {0.f, 0.f, 0.f, 0.f};
    #pragma unroll 4
    for (int ii = 0; ii < 64; ii++) {
        const int i = i0 + ii;
        const float xi = xs[i], vi = vs[i];
        #pragma unroll
        for (int j = 0; j < 4; j++) {
            float tv = xi * vc[j] + xc[j] * vi;
            float s = sqrt_ap(fmaxf(fabsf(tv), 1e-8f));
            d[j] += (tv != 0.f) ? s : 0.f;
        }
    }
    #pragma unroll
    for (int j = 0; j < 4; j++) pden[r * 256 + 4 * cg + j] = d[j];
    __syncthreads();

    {
        float den = pden[t] + pden[256 + t] + pden[512 + t] + pden[768 + t];
        float id = rcp_ap(den + 1e-7f);
        idn[t] = id;
        us[t] = xs[t] * id;
    }
    __syncthreads();

    float ic[4];
    #pragma unroll
    for (int j = 0; j < 4; j++) ic[j] = idn[4 * cg + j];
    float h[4] = {0.f, 0.f, 0.f, 0.f};
    float* ap = adj + (size_t)bc * 65536 + 4 * cg;

    #pragma unroll 4
    for (int ii = 0; ii < 64; ii++) {
        const int i = i0 + ii;
        const float xi = xs[i], vi = vs[i], usi = us[i];
        float4 o;
        #pragma unroll
        for (int j = 0; j < 4; j++) {
            float tv = xi * vc[j] + xc[j] * vi;
            float s = sqrt_ap(fmaxf(fabsf(tv), 1e-8f));
            float a = (tv != 0.f) ? copysignf(s, tv) : 0.f;
            (&o.x)[j] = a * ic[j];
            h[j] = fmaf(a, usi, h[j]);
        }
        __stcs((float4*)(ap + (size_t)i * 256), o);
    }
    #pragma unroll
    for (int j = 0; j < 4; j++) pden[r * 256 + 4 * cg + j] = h[j];
    __syncthreads();

    float hs = pden[t] + pden[256 + t] + pden[512 + t] + pden[768 + t];
    g_z[b * 2048 + c * 256 + t] = hs;
}

// ---------------------------------------------------------------------------
// Kernel 3: out = z @ W^T  (M=256, N=2048, K=2048), 64x64x32 tiles.
// Dup-A smem layout: Ad[k][2m]=Ad[k][2m+1]=A[m][k]  -> FFMA2 a-operand is a
// direct (a,a) LDS.64 broadcast; B LDS.64 is 256B-contiguous per warp.
// Inner loop: 6 LDS.64 + 8 FFMA2 = 14 instr < 16-cyc FMA2-pipe demand.
// ---------------------------------------------------------------------------
__device__ __forceinline__ unsigned long long pack2f(float v) {
    unsigned long long r;
    asm("mov.b64 %0, {%1, %2};" : "=l"(r) : "f"(v), "f"(v));
    return r;
}
__device__ __forceinline__ void ffma2(unsigned long long& d,
                                      unsigned long long a, unsigned long long b) {
    asm("fma.rn.f32x2 %0, %1, %2, %0;" : "+l"(d) : "l"(a), "l"(b));
}

__global__ __launch_bounds__(256) void k3_gemm(
    const float* __restrict__ W, float* __restrict__ out)
{
    __shared__ float Ad[2][32 * 128];   // dup A: [k][2m]   16 KB / buf
    __shared__ float Bs[2][32 * 64];    // [k][n]            8 KB / buf
    const int t = threadIdx.x;
    const int tx = t & 15, ty = t >> 4;
    const int bn = blockIdx.x * 64, bm = blockIdx.y * 64;
    const int rowL = t >> 2, q = t & 3;     // loader mapping: row 0..63, quad 0..3

    const float* Ag = g_z + (bm + rowL) * 2048 + 4 * q;
    const float* Bg = W + (size_t)(bn + rowL) * 2048 + 4 * q;

    float4 a0 = *(const float4*)Ag,        a1 = *(const float4*)(Ag + 16);
    float4 b0 = *(const float4*)Bg,        b1 = *(const float4*)(Bg + 16);

    unsigned long long acc[4][2];
    #pragma unroll
    for (int m = 0; m < 4; m++) { acc[m][0] = 0ull; acc[m][1] = 0ull; }

    int buf = 0;
    for (int kt = 0; kt < 64; kt++) {
        #pragma unroll
        for (int j = 0; j < 4; j++) {
            *(unsigned long long*)&Ad[buf][(4 * q + j) * 128 + 2 * rowL]      = pack2f((&a0.x)[j]);
            *(unsigned long long*)&Ad[buf][(4 * q + 16 + j) * 128 + 2 * rowL] = pack2f((&a1.x)[j]);
            Bs[buf][(4 * q + j) * 64 + rowL]      = (&b0.x)[j];
            Bs[buf][(4 * q + 16 + j) * 64 + rowL] = (&b1.x)[j];
        }
        __syncthreads();

        if (kt < 63) {
            const float* Ag2 = Ag + (kt + 1) * 32;
            const float* Bg2 = Bg + (kt + 1) * 32;
            a0 = *(const float4*)Ag2;  a1 = *(const float4*)(Ag2 + 16);
            b0 = *(const float4*)Bg2;  b1 = *(const float4*)(Bg2 + 16);
        }

        #pragma unroll 16
        for (int k = 0; k < 32; k++) {
            const unsigned long long* ar =
                (const unsigned long long*)&Ad[buf][k * 128 + 8 * ty];
            const unsigned long long* br =
                (const unsigned long long*)&Bs[buf][k * 64 + 4 * tx];
            unsigned long long A0 = ar[0], A1 = ar[1], A2 = ar[2], A3 = ar[3];
            unsigned long long B0 = br[0], B1 = br[1];
            ffma2(acc[0][0], A0, B0); ffma2(acc[0][1], A0, B1);
            ffma2(acc[1][0], A1, B0); ffma2(acc[1][1], A1, B1);
            ffma2(acc[2][0], A2, B0); ffma2(acc[2][1], A2, B1);
            ffma2(acc[3][0], A3, B0); ffma2(acc[3][1], A3, B1);
        }
        buf ^= 1;
        __syncthreads();
    }

    #pragma unroll
    for (int m = 0; m < 4; m++) {
        const int row = bm + 4 * ty + m;
        float4 o;
        *(float2*)&o.x = *(float2*)&acc[m][0];
        *(float2*)&o.z = *(float2*)&acc[m][1];
        *(float4*)(out + (size_t)row * 2048 + bn + 4 * tx) = o;
    }
}

// ---------------------------------------------------------------------------
// Launch: output layout = concat(out (B*OC*OF), adj (B*C*F*F)) in fp32.
// 4 launches/call => ncu capture slot (index 6) lands on k2.
// ---------------------------------------------------------------------------
extern "C" void kernel_launch(void* const* d_in, const int* in_sizes, int n_in,
                              void* d_out, int out_size)
{
    const float* x   = (const float*)d_in[0];
    const float* nb  = (const float*)d_in[1];
    const float* Wa1 = (const float*)d_in[2];
    const float* Wa2 = (const float*)d_in[3];
    const float* Wc  = (const float*)d_in[4];
    float* out = (float*)d_out;
    float* adj = out + (size_t)B_ * OC_ * OF_;

    k1a_logits<<<B_ * 4, 256>>>(nb, Wa2);
    k1b_softmax<<<B_, 256>>>(x, Wa1);
    k2_adj<<<B_ * C_, 256>>>(x, nb, adj);
    k3_gemm<<<dim3(2048 / 64, 256 / 64), 256>>>(Wc, out);
}

// round 6
// speedup vs baseline: 1.1353x; 1.1353x over previous
#include <cuda_runtime.h>
#include <cstdint>
#include <cstddef>

#define B_  256
#define C_  4
#define N_  64
#define F_  256
#define OC_ 8
#define OF_ 256
#define KSPLIT 4

typedef unsigned long long ull;

// Scratch (no allocations allowed)
__device__ float g_z[B_ * 2 * C_ * F_];        // 2 MB : concat(h, x) rows for GEMM
__device__ float g_w[B_ * N_];                 // softmax weights
__device__ float g_s2[B_ * N_];                // raw neighbor logits
__device__ float g_part[KSPLIT * B_ * OC_ * OF_];  // 8 MB : split-K partials

__device__ __forceinline__ float sqrt_ap(float v) {
    float r; asm("sqrt.approx.f32 %0, %1;" : "=f"(r) : "f"(v)); return r;
}
__device__ __forceinline__ float rcp_ap(float v) {
    float r; asm("rcp.approx.f32 %0, %1;" : "=f"(r) : "f"(v)); return r;
}
__device__ __forceinline__ ull pack2f(float v) {
    ull r; asm("mov.b64 %0, {%1, %2};" : "=l"(r) : "f"(v), "f"(v)); return r;
}
__device__ __forceinline__ void ffma2(ull& d, ull a, ull b) {
    asm("fma.rn.f32x2 %0, %1, %2, %0;" : "+l"(d) : "l"(a), "l"(b));
}

// ---------------------------------------------------------------------------
// Kernel 1a: s2 logits. Grid 1024 = (b, quarter); each block: 16 neighbors.
// ---------------------------------------------------------------------------
__global__ __launch_bounds__(256) void k1a_logits(
    const float* __restrict__ nb, const float* __restrict__ Wa2)
{
    __shared__ float ws2[256];
    const int b = blockIdx.x >> 2, quarter = blockIdx.x & 3;
    const int t = threadIdx.x;
    const int lane = t & 31, w = t >> 5;

    ws2[t] = Wa2[t] + Wa2[256 + t] + Wa2[512 + t] + Wa2[768 + t];
    __syncthreads();

    const float* nbb = nb + (size_t)b * 65536;
    #pragma unroll
    for (int j = 0; j < 2; j++) {
        const int n = quarter * 16 + w * 2 + j;
        const float4* np = (const float4*)(nbb + n * 1024);
        float acc = 0.f;
        #pragma unroll
        for (int it = 0; it < 8; it++) {
            float4 q = np[it * 32 + lane];
            int f = (it * 128 + lane * 4) & 255;
            acc += q.x * ws2[f] + q.y * ws2[f + 1] + q.z * ws2[f + 2] + q.w * ws2[f + 3];
        }
        #pragma unroll
        for (int o = 16; o > 0; o >>= 1) acc += __shfl_xor_sync(0xffffffffu, acc, o);
        if (lane == 0) g_s2[b * 64 + n] = acc;
    }
}

// ---------------------------------------------------------------------------
// Kernel 1b: s1 + softmax weights; copy x into z channels 4..7. Grid 256.
// ---------------------------------------------------------------------------
__global__ __launch_bounds__(256) void k1b_softmax(
    const float* __restrict__ x, const float* __restrict__ Wa1)
{
    __shared__ float red[8];
    const int b = blockIdx.x;
    const int t = threadIdx.x;
    const int lane = t & 31, w = t >> 5;

    float w1 = Wa1[t] + Wa1[256 + t] + Wa1[512 + t] + Wa1[768 + t];

    float xs = 0.f;
    #pragma unroll
    for (int c = 0; c < 4; c++) {
        float xv = x[(b * 4 + c) * 256 + t];
        g_z[b * 2048 + (4 + c) * 256 + t] = xv;
        xs += xv;
    }
    float p = xs * w1;
    #pragma unroll
    for (int o = 16; o > 0; o >>= 1) p += __shfl_xor_sync(0xffffffffu, p, o);
    if (lane == 0) red[w] = p;
    __syncthreads();

    if (w == 0) {
        float s1v = red[lane & 7];
        #pragma unroll
        for (int o = 4; o > 0; o >>= 1) s1v += __shfl_xor_sync(0xffffffffu, s1v, o);
        float l0 = s1v * g_s2[b * 64 + lane];
        float l1 = s1v * g_s2[b * 64 + lane + 32];
        float m = fmaxf(l0, l1);
        #pragma unroll
        for (int o = 16; o > 0; o >>= 1) m = fmaxf(m, __shfl_xor_sync(0xffffffffu, m, o));
        float e0 = __expf(l0 - m), e1 = __expf(l1 - m);
        float s = e0 + e1;
        #pragma unroll
        for (int o = 16; o > 0; o >>= 1) s += __shfl_xor_sync(0xffffffffu, s, o);
        float inv = 1.f / s;
        g_w[b * 64 + lane]      = e0 * inv;
        g_w[b * 64 + lane + 32] = e1 * inv;
    }
}

// ---------------------------------------------------------------------------
// Kernel 2: v (L2-resident neighbor) + adj + fused h.  (unchanged this round)
// ---------------------------------------------------------------------------
__global__ __launch_bounds__(256) void k2_adj(
    const float* __restrict__ x, const float* __restrict__ nb,
    float* __restrict__ adj)
{
    __shared__ float xs[256], vs[256], us[256], idn[256];
    __shared__ float wsm[64];
    __shared__ float pden[4 * 256];

    const int bc = blockIdx.x;
    const int b = bc >> 2, c = bc & 3;
    const int t = threadIdx.x;

    if (t < 64) wsm[t] = g_w[b * 64 + t];
    xs[t] = x[bc * 256 + t];
    __syncthreads();

    {
        const float* nbp = nb + ((size_t)b * 256 + c) * 256 + t;
        float acc = 0.f;
        #pragma unroll 8
        for (int n = 0; n < 64; n++) acc += wsm[n] * nbp[(size_t)n * 1024];
        vs[t] = acc;
    }
    __syncthreads();

    const int r = t >> 6, cg = t & 63;
    const int i0 = r * 64;
    float xc[4], vc[4];
    #pragma unroll
    for (int j = 0; j < 4; j++) { xc[j] = xs[4 * cg + j]; vc[j] = vs[4 * cg + j]; }

    float d[4] = {0.f, 0.f, 0.f, 0.f};
    #pragma unroll 4
    for (int ii = 0; ii < 64; ii++) {
        const int i = i0 + ii;
        const float xi = xs[i], vi = vs[i];
        #pragma unroll
        for (int j = 0; j < 4; j++) {
            float tv = xi * vc[j] + xc[j] * vi;
            float s = sqrt_ap(fmaxf(fabsf(tv), 1e-8f));
            d[j] += (tv != 0.f) ? s : 0.f;
        }
    }
    #pragma unroll
    for (int j = 0; j < 4; j++) pden[r * 256 + 4 * cg + j] = d[j];
    __syncthreads();

    {
        float den = pden[t] + pden[256 + t] + pden[512 + t] + pden[768 + t];
        float id = rcp_ap(den + 1e-7f);
        idn[t] = id;
        us[t] = xs[t] * id;
    }
    __syncthreads();

    float ic[4];
    #pragma unroll
    for (int j = 0; j < 4; j++) ic[j] = idn[4 * cg + j];
    float h[4] = {0.f, 0.f, 0.f, 0.f};
    float* ap = adj + (size_t)bc * 65536 + 4 * cg;

    #pragma unroll 4
    for (int ii = 0; ii < 64; ii++) {
        const int i = i0 + ii;
        const float xi = xs[i], vi = vs[i], usi = us[i];
        float4 o;
        #pragma unroll
        for (int j = 0; j < 4; j++) {
            float tv = xi * vc[j] + xc[j] * vi;
            float s = sqrt_ap(fmaxf(fabsf(tv), 1e-8f));
            float a = (tv != 0.f) ? copysignf(s, tv) : 0.f;
            (&o.x)[j] = a * ic[j];
            h[j] = fmaf(a, usi, h[j]);
        }
        __stcs((float4*)(ap + (size_t)i * 256), o);
    }
    #pragma unroll
    for (int j = 0; j < 4; j++) pden[r * 256 + 4 * cg + j] = h[j];
    __syncthreads();

    float hs = pden[t] + pden[256 + t] + pden[512 + t] + pden[768 + t];
    g_z[b * 2048 + c * 256 + t] = hs;
}

// ---------------------------------------------------------------------------
// Kernel 3: split-K GEMM partials.  grid (32 n-tiles, 2 m-tiles, 4 k-splits),
// 128 threads, tile 128x64, per-thread m8xn8.
// Per warp k-step: 8 broadcast A-LDS.64 + 4 narrow B-LDS.64 = 12 wf
// vs 32 FFMA2  ->  FMA2-pipe-bound.
// ---------------------------------------------------------------------------
__global__ __launch_bounds__(128) void k3_gemm(
    const float* __restrict__ W)
{
    __shared__ float Ad[2][16 * 256];   // [k][2m] dup, 16 KB/buf
    __shared__ float Bs[2][16 * 64];    // [k][n],   4 KB/buf
    const int t = threadIdx.x;
    const int w = t >> 5, lane = t & 31;
    const int bn = blockIdx.x * 64;
    const int bm = blockIdx.y * 128;
    const int ks = blockIdx.z;

    const float* Ag = g_z + (bm + t) * 2048 + ks * 512;
    const float* Bg = W + (size_t)(bn + (t >> 1)) * 2048 + ks * 512 + (t & 1) * 8;

    const int wm = (w & 1) * 64, wn = (w >> 1) * 32;
    const int lm = (lane >> 2) * 8, ln = (lane & 3) * 8;

    float4 a_pf[4], b_pf[2];
    #pragma unroll
    for (int i = 0; i < 4; i++) a_pf[i] = *(const float4*)(Ag + i * 4);
    b_pf[0] = *(const float4*)Bg;
    b_pf[1] = *(const float4*)(Bg + 4);

    ull acc[8][4];
    #pragma unroll
    for (int m = 0; m < 8; m++)
        #pragma unroll
        for (int n = 0; n < 4; n++) acc[m][n] = 0ull;

    int buf = 0;
    for (int ch = 0; ch < 32; ch++) {
        // stage chunk: A duplicated, B transposed
        #pragma unroll
        for (int i = 0; i < 4; i++)
            #pragma unroll
            for (int j = 0; j < 4; j++)
                *(ull*)&Ad[buf][(i * 4 + j) * 256 + 2 * t] = pack2f((&a_pf[i].x)[j]);
        #pragma unroll
        for (int i = 0; i < 2; i++)
            #pragma unroll
            for (int j = 0; j < 4; j++)
                Bs[buf][((t & 1) * 8 + i * 4 + j) * 64 + (t >> 1)] = (&b_pf[i].x)[j];
        __syncthreads();

        if (ch < 31) {
            const float* Ag2 = Ag + (ch + 1) * 16;
            const float* Bg2 = Bg + (ch + 1) * 16;
            #pragma unroll
            for (int i = 0; i < 4; i++) a_pf[i] = *(const float4*)(Ag2 + i * 4);
            b_pf[0] = *(const float4*)Bg2;
            b_pf[1] = *(const float4*)(Bg2 + 4);
        }

        #pragma unroll
        for (int k = 0; k < 16; k++) {
            const ull* ar = (const ull*)&Ad[buf][k * 256 + 2 * (wm + lm)];
            const ull* br = (const ull*)&Bs[buf][k * 64 + wn + ln];
            ull A0 = ar[0], A1 = ar[1], A2 = ar[2], A3 = ar[3];
            ull A4 = ar[4], A5 = ar[5], A6 = ar[6], A7 = ar[7];
            ull Bv0 = br[0], Bv1 = br[1], Bv2 = br[2], Bv3 = br[3];
            ffma2(acc[0][0], A0, Bv0); ffma2(acc[0][1], A0, Bv1); ffma2(acc[0][2], A0, Bv2); ffma2(acc[0][3], A0, Bv3);
            ffma2(acc[1][0], A1, Bv0); ffma2(acc[1][1], A1, Bv1); ffma2(acc[1][2], A1, Bv2); ffma2(acc[1][3], A1, Bv3);
            ffma2(acc[2][0], A2, Bv0); ffma2(acc[2][1], A2, Bv1); ffma2(acc[2][2], A2, Bv2); ffma2(acc[2][3], A2, Bv3);
            ffma2(acc[3][0], A3, Bv0); ffma2(acc[3][1], A3, Bv1); ffma2(acc[3][2], A3, Bv2); ffma2(acc[3][3], A3, Bv3);
            ffma2(acc[4][0], A4, Bv0); ffma2(acc[4][1], A4, Bv1); ffma2(acc[4][2], A4, Bv2); ffma2(acc[4][3], A4, Bv3);
            ffma2(acc[5][0], A5, Bv0); ffma2(acc[5][1], A5, Bv1); ffma2(acc[5][2], A5, Bv2); ffma2(acc[5][3], A5, Bv3);
            ffma2(acc[6][0], A6, Bv0); ffma2(acc[6][1], A6, Bv1); ffma2(acc[6][2], A6, Bv2); ffma2(acc[6][3], A6, Bv3);
            ffma2(acc[7][0], A7, Bv0); ffma2(acc[7][1], A7, Bv1); ffma2(acc[7][2], A7, Bv2); ffma2(acc[7][3], A7, Bv3);
        }
        buf ^= 1;
        __syncthreads();
    }

    // write split-K partial (plain STG.128, no atomics)
    float* pp = g_part + (size_t)ks * 524288;
    #pragma unroll
    for (int m = 0; m < 8; m++) {
        const int row = bm + wm + lm + m;
        float* op = pp + (size_t)row * 2048 + bn + wn + ln;
        float4 o0, o1;
        *(float2*)&o0.x = *(float2*)&acc[m][0];
        *(float2*)&o0.z = *(float2*)&acc[m][1];
        *(float2*)&o1.x = *(float2*)&acc[m][2];
        *(float2*)&o1.z = *(float2*)&acc[m][3];
        *(float4*)op = o0;
        *(float4*)(op + 4) = o1;
    }
}

// ---------------------------------------------------------------------------
// Kernel 4: sum the 4 split-K partials into out. 512K outputs.
// ---------------------------------------------------------------------------
__global__ __launch_bounds__(256) void k4_reduce(float* __restrict__ out)
{
    const int i = (blockIdx.x * 256 + threadIdx.x) * 4;
    const float4 p0 = *(const float4*)(g_part + i);
    const float4 p1 = *(const float4*)(g_part + 524288 + i);
    const float4 p2 = *(const float4*)(g_part + 2 * 524288 + i);
    const float4 p3 = *(const float4*)(g_part + 3 * 524288 + i);
    float4 o;
    o.x = (p0.x + p1.x) + (p2.x + p3.x);
    o.y = (p0.y + p1.y) + (p2.y + p3.y);
    o.z = (p0.z + p1.z) + (p2.z + p3.z);
    o.w = (p0.w + p1.w) + (p2.w + p3.w);
    *(float4*)(out + i) = o;
}

// ---------------------------------------------------------------------------
// Launch: output layout = concat(out (B*OC*OF), adj (B*C*F*F)) in fp32.
// ---------------------------------------------------------------------------
extern "C" void kernel_launch(void* const* d_in, const int* in_sizes, int n_in,
                              void* d_out, int out_size)
{
    const float* x   = (const float*)d_in[0];
    const float* nb  = (const float*)d_in[1];
    const float* Wa1 = (const float*)d_in[2];
    const float* Wa2 = (const float*)d_in[3];
    const float* Wc  = (const float*)d_in[4];
    float* out = (float*)d_out;
    float* adj = out + (size_t)B_ * OC_ * OF_;

    k1a_logits<<<B_ * 4, 256>>>(nb, Wa2);
    k1b_softmax<<<B_, 256>>>(x, Wa1);
    k2_adj<<<B_ * C_, 256>>>(x, nb, adj);
    k3_gemm<<<dim3(32, 2, KSPLIT), 128>>>(Wc);
    k4_reduce<<<512, 256>>>(out);
}

// round 7
// speedup vs baseline: 1.1758x; 1.0357x over previous
#include <cuda_runtime.h>
#include <cstdint>
#include <cstddef>

#define B_  256
#define C_  4
#define N_  64
#define F_  256
#define OC_ 8
#define OF_ 256
#define KSPLIT 4

typedef unsigned long long ull;

// Scratch (no allocations allowed)
__device__ float g_z[B_ * 2 * C_ * F_];        // 2 MB : concat(h, x) rows for GEMM
__device__ float g_w[B_ * N_];                 // softmax weights
__device__ float g_s2[B_ * N_];                // raw neighbor logits
__device__ float g_part[KSPLIT * B_ * OC_ * OF_];  // 8 MB : split-K partials

__device__ __forceinline__ float sqrt_ap(float v) {
    float r; asm("sqrt.approx.f32 %0, %1;" : "=f"(r) : "f"(v)); return r;
}
__device__ __forceinline__ float rcp_ap(float v) {
    float r; asm("rcp.approx.f32 %0, %1;" : "=f"(r) : "f"(v)); return r;
}
__device__ __forceinline__ ull pack2f(float v) {
    ull r; asm("mov.b64 %0, {%1, %2};" : "=l"(r) : "f"(v), "f"(v)); return r;
}
__device__ __forceinline__ void ffma2(ull& d, ull a, ull b) {
    asm("fma.rn.f32x2 %0, %1, %2, %0;" : "+l"(d) : "l"(a), "l"(b));
}

// ---------------------------------------------------------------------------
// Kernel 1a: s2 logits. Grid 1024 = (b, quarter); each block: 16 neighbors.
// ---------------------------------------------------------------------------
__global__ __launch_bounds__(256) void k1a_logits(
    const float* __restrict__ nb, const float* __restrict__ Wa2)
{
    __shared__ float ws2[256];
    const int b = blockIdx.x >> 2, quarter = blockIdx.x & 3;
    const int t = threadIdx.x;
    const int lane = t & 31, w = t >> 5;

    ws2[t] = Wa2[t] + Wa2[256 + t] + Wa2[512 + t] + Wa2[768 + t];
    __syncthreads();

    const float* nbb = nb + (size_t)b * 65536;
    #pragma unroll
    for (int j = 0; j < 2; j++) {
        const int n = quarter * 16 + w * 2 + j;
        const float4* np = (const float4*)(nbb + n * 1024);
        float acc = 0.f;
        #pragma unroll
        for (int it = 0; it < 8; it++) {
            float4 q = np[it * 32 + lane];
            int f = (it * 128 + lane * 4) & 255;
            acc += q.x * ws2[f] + q.y * ws2[f + 1] + q.z * ws2[f + 2] + q.w * ws2[f + 3];
        }
        #pragma unroll
        for (int o = 16; o > 0; o >>= 1) acc += __shfl_xor_sync(0xffffffffu, acc, o);
        if (lane == 0) g_s2[b * 64 + n] = acc;
    }
}

// ---------------------------------------------------------------------------
// Kernel 1b: s1 + softmax weights; copy x into z channels 4..7. Grid 256.
// ---------------------------------------------------------------------------
__global__ __launch_bounds__(256) void k1b_softmax(
    const float* __restrict__ x, const float* __restrict__ Wa1)
{
    __shared__ float red[8];
    const int b = blockIdx.x;
    const int t = threadIdx.x;
    const int lane = t & 31, w = t >> 5;

    float w1 = Wa1[t] + Wa1[256 + t] + Wa1[512 + t] + Wa1[768 + t];

    float xs = 0.f;
    #pragma unroll
    for (int c = 0; c < 4; c++) {
        float xv = x[(b * 4 + c) * 256 + t];
        g_z[b * 2048 + (4 + c) * 256 + t] = xv;
        xs += xv;
    }
    float p = xs * w1;
    #pragma unroll
    for (int o = 16; o > 0; o >>= 1) p += __shfl_xor_sync(0xffffffffu, p, o);
    if (lane == 0) red[w] = p;
    __syncthreads();

    if (w == 0) {
        float s1v = red[lane & 7];
        #pragma unroll
        for (int o = 4; o > 0; o >>= 1) s1v += __shfl_xor_sync(0xffffffffu, s1v, o);
        float l0 = s1v * g_s2[b * 64 + lane];
        float l1 = s1v * g_s2[b * 64 + lane + 32];
        float m = fmaxf(l0, l1);
        #pragma unroll
        for (int o = 16; o > 0; o >>= 1) m = fmaxf(m, __shfl_xor_sync(0xffffffffu, m, o));
        float e0 = __expf(l0 - m), e1 = __expf(l1 - m);
        float s = e0 + e1;
        #pragma unroll
        for (int o = 16; o > 0; o >>= 1) s += __shfl_xor_sync(0xffffffffu, s, o);
        float inv = 1.f / s;
        g_w[b * 64 + lane]      = e0 * inv;
        g_w[b * 64 + lane + 32] = e1 * inv;
    }
}

// ---------------------------------------------------------------------------
// Kernel 2: v (L2-resident neighbor) + adj + fused h.  (unchanged this round)
// ---------------------------------------------------------------------------
__global__ __launch_bounds__(256) void k2_adj(
    const float* __restrict__ x, const float* __restrict__ nb,
    float* __restrict__ adj)
{
    __shared__ float xs[256], vs[256], us[256], idn[256];
    __shared__ float wsm[64];
    __shared__ float pden[4 * 256];

    const int bc = blockIdx.x;
    const int b = bc >> 2, c = bc & 3;
    const int t = threadIdx.x;

    if (t < 64) wsm[t] = g_w[b * 64 + t];
    xs[t] = x[bc * 256 + t];
    __syncthreads();

    {
        const float* nbp = nb + ((size_t)b * 256 + c) * 256 + t;
        float acc = 0.f;
        #pragma unroll 8
        for (int n = 0; n < 64; n++) acc += wsm[n] * nbp[(size_t)n * 1024];
        vs[t] = acc;
    }
    __syncthreads();

    const int r = t >> 6, cg = t & 63;
    const int i0 = r * 64;
    float xc[4], vc[4];
    #pragma unroll
    for (int j = 0; j < 4; j++) { xc[j] = xs[4 * cg + j]; vc[j] = vs[4 * cg + j]; }

    float d[4] = {0.f, 0.f, 0.f, 0.f};
    #pragma unroll 4
    for (int ii = 0; ii < 64; ii++) {
        const int i = i0 + ii;
        const float xi = xs[i], vi = vs[i];
        #pragma unroll
        for (int j = 0; j < 4; j++) {
            float tv = xi * vc[j] + xc[j] * vi;
            float s = sqrt_ap(fmaxf(fabsf(tv), 1e-8f));
            d[j] += (tv != 0.f) ? s : 0.f;
        }
    }
    #pragma unroll
    for (int j = 0; j < 4; j++) pden[r * 256 + 4 * cg + j] = d[j];
    __syncthreads();

    {
        float den = pden[t] + pden[256 + t] + pden[512 + t] + pden[768 + t];
        float id = rcp_ap(den + 1e-7f);
        idn[t] = id;
        us[t] = xs[t] * id;
    }
    __syncthreads();

    float ic[4];
    #pragma unroll
    for (int j = 0; j < 4; j++) ic[j] = idn[4 * cg + j];
    float h[4] = {0.f, 0.f, 0.f, 0.f};
    float* ap = adj + (size_t)bc * 65536 + 4 * cg;

    #pragma unroll 4
    for (int ii = 0; ii < 64; ii++) {
        const int i = i0 + ii;
        const float xi = xs[i], vi = vs[i], usi = us[i];
        float4 o;
        #pragma unroll
        for (int j = 0; j < 4; j++) {
            float tv = xi * vc[j] + xc[j] * vi;
            float s = sqrt_ap(fmaxf(fabsf(tv), 1e-8f));
            float a = (tv != 0.f) ? copysignf(s, tv) : 0.f;
            (&o.x)[j] = a * ic[j];
            h[j] = fmaf(a, usi, h[j]);
        }
        __stcs((float4*)(ap + (size_t)i * 256), o);
    }
    #pragma unroll
    for (int j = 0; j < 4; j++) pden[r * 256 + 4 * cg + j] = h[j];
    __syncthreads();

    float hs = pden[t] + pden[256 + t] + pden[512 + t] + pden[768 + t];
    g_z[b * 2048 + c * 256 + t] = hs;
}

// ---------------------------------------------------------------------------
// Kernel 3: split-K GEMM partials. grid (32, 2, 4), 128 thr, tile 128x64,
// per-thread m8xn8.
// Dup-A layout with bank swizzle: soff(m) = 2m + 2*(m>>4), row stride 272.
// Per-warp A addresses land on distinct bank pairs -> 1 wavefront per
// A LDS.64 (round 6 layout was 4-way conflicted -> L1-bound at 78%).
// ---------------------------------------------------------------------------
#define AROW 272
#define SOFF(m) (2 * (m) + 2 * ((m) >> 4))

__global__ __launch_bounds__(128) void k3_gemm(
    const float* __restrict__ W)
{
    __shared__ float Ad[2][16 * AROW];  // dup A, swizzled: 17.4 KB/buf
    __shared__ float Bs[2][16 * 64];    // [k][n]: 4 KB/buf
    const int t = threadIdx.x;
    const int w = t >> 5, lane = t & 31;
    const int bn = blockIdx.x * 64;
    const int bm = blockIdx.y * 128;
    const int ks = blockIdx.z;

    const float* Ag = g_z + (bm + t) * 2048 + ks * 512;
    const float* Bg = W + (size_t)(bn + (t >> 1)) * 2048 + ks * 512 + (t & 1) * 8;

    const int wm = (w & 1) * 64, wn = (w >> 1) * 32;
    const int lm = (lane >> 2) * 8, ln = (lane & 3) * 8;
    const int s_off = SOFF(t);              // store column for my m-row (=t)
    const int a_off = SOFF(wm + lm);        // load base for my 8 m's (no 16-cross)

    float4 a_pf[4], b_pf[2];
    #pragma unroll
    for (int i = 0; i < 4; i++) a_pf[i] = *(const float4*)(Ag + i * 4);
    b_pf[0] = *(const float4*)Bg;
    b_pf[1] = *(const float4*)(Bg + 4);

    ull acc[8][4];
    #pragma unroll
    for (int m = 0; m < 8; m++)
        #pragma unroll
        for (int n = 0; n < 4; n++) acc[m][n] = 0ull;

    int buf = 0;
    for (int ch = 0; ch < 32; ch++) {
        // stage chunk: A duplicated+swizzled, B transposed
        #pragma unroll
        for (int i = 0; i < 4; i++)
            #pragma unroll
            for (int j = 0; j < 4; j++)
                *(ull*)&Ad[buf][(i * 4 + j) * AROW + s_off] = pack2f((&a_pf[i].x)[j]);
        #pragma unroll
        for (int i = 0; i < 2; i++)
            #pragma unroll
            for (int j = 0; j < 4; j++)
                Bs[buf][((t & 1) * 8 + i * 4 + j) * 64 + (t >> 1)] = (&b_pf[i].x)[j];
        __syncthreads();

        if (ch < 31) {
            const float* Ag2 = Ag + (ch + 1) * 16;
            const float* Bg2 = Bg + (ch + 1) * 16;
            #pragma unroll
            for (int i = 0; i < 4; i++) a_pf[i] = *(const float4*)(Ag2 + i * 4);
            b_pf[0] = *(const float4*)Bg2;
            b_pf[1] = *(const float4*)(Bg2 + 4);
        }

        #pragma unroll
        for (int k = 0; k < 16; k++) {
            const ull* ar = (const ull*)&Ad[buf][k * AROW + a_off];
            const ull* br = (const ull*)&Bs[buf][k * 64 + wn + ln];
            ull A0 = ar[0], A1 = ar[1], A2 = ar[2], A3 = ar[3];
            ull A4 = ar[4], A5 = ar[5], A6 = ar[6], A7 = ar[7];
            ull Bv0 = br[0], Bv1 = br[1], Bv2 = br[2], Bv3 = br[3];
            ffma2(acc[0][0], A0, Bv0); ffma2(acc[0][1], A0, Bv1); ffma2(acc[0][2], A0, Bv2); ffma2(acc[0][3], A0, Bv3);
            ffma2(acc[1][0], A1, Bv0); ffma2(acc[1][1], A1, Bv1); ffma2(acc[1][2], A1, Bv2); ffma2(acc[1][3], A1, Bv3);
            ffma2(acc[2][0], A2, Bv0); ffma2(acc[2][1], A2, Bv1); ffma2(acc[2][2], A2, Bv2); ffma2(acc[2][3], A2, Bv3);
            ffma2(acc[3][0], A3, Bv0); ffma2(acc[3][1], A3, Bv1); ffma2(acc[3][2], A3, Bv2); ffma2(acc[3][3], A3, Bv3);
            ffma2(acc[4][0], A4, Bv0); ffma2(acc[4][1], A4, Bv1); ffma2(acc[4][2], A4, Bv2); ffma2(acc[4][3], A4, Bv3);
            ffma2(acc[5][0], A5, Bv0); ffma2(acc[5][1], A5, Bv1); ffma2(acc[5][2], A5, Bv2); ffma2(acc[5][3], A5, Bv3);
            ffma2(acc[6][0], A6, Bv0); ffma2(acc[6][1], A6, Bv1); ffma2(acc[6][2], A6, Bv2); ffma2(acc[6][3], A6, Bv3);
            ffma2(acc[7][0], A7, Bv0); ffma2(acc[7][1], A7, Bv1); ffma2(acc[7][2], A7, Bv2); ffma2(acc[7][3], A7, Bv3);
        }
        buf ^= 1;
        __syncthreads();
    }

    // write split-K partial (plain STG.128, no atomics)
    float* pp = g_part + (size_t)ks * 524288;
    #pragma unroll
    for (int m = 0; m < 8; m++) {
        const int row = bm + wm + lm + m;
        float* op = pp + (size_t)row * 2048 + bn + wn + ln;
        float4 o0, o1;
        *(float2*)&o0.x = *(float2*)&acc[m][0];
        *(float2*)&o0.z = *(float2*)&acc[m][1];
        *(float2*)&o1.x = *(float2*)&acc[m][2];
        *(float2*)&o1.z = *(float2*)&acc[m][3];
        *(float4*)op = o0;
        *(float4*)(op + 4) = o1;
    }
}

// ---------------------------------------------------------------------------
// Kernel 4: sum the 4 split-K partials into out. 512K outputs.
// ---------------------------------------------------------------------------
__global__ __launch_bounds__(256) void k4_reduce(float* __restrict__ out)
{
    const int i = (blockIdx.x * 256 + threadIdx.x) * 4;
    const float4 p0 = *(const float4*)(g_part + i);
    const float4 p1 = *(const float4*)(g_part + 524288 + i);
    const float4 p2 = *(const float4*)(g_part + 2 * 524288 + i);
    const float4 p3 = *(const float4*)(g_part + 3 * 524288 + i);
    float4 o;
    o.x = (p0.x + p1.x) + (p2.x + p3.x);
    o.y = (p0.y + p1.y) + (p2.y + p3.y);
    o.z = (p0.z + p1.z) + (p2.z + p3.z);
    o.w = (p0.w + p1.w) + (p2.w + p3.w);
    *(float4*)(out + i) = o;
}

// ---------------------------------------------------------------------------
// Launch: output layout = concat(out (B*OC*OF), adj (B*C*F*F)) in fp32.
// ---------------------------------------------------------------------------
extern "C" void kernel_launch(void* const* d_in, const int* in_sizes, int n_in,
                              void* d_out, int out_size)
{
    const float* x   = (const float*)d_in[0];
    const float* nb  = (const float*)d_in[1];
    const float* Wa1 = (const float*)d_in[2];
    const float* Wa2 = (const float*)d_in[3];
    const float* Wc  = (const float*)d_in[4];
    float* out = (float*)d_out;
    float* adj = out + (size_t)B_ * OC_ * OF_;

    k1a_logits<<<B_ * 4, 256>>>(nb, Wa2);
    k1b_softmax<<<B_, 256>>>(x, Wa1);
    k2_adj<<<B_ * C_, 256>>>(x, nb, adj);
    k3_gemm<<<dim3(32, 2, KSPLIT), 128>>>(Wc);
    k4_reduce<<<512, 256>>>(out);
}